// round 4
// baseline (speedup 1.0000x reference)
#include <cuda_runtime.h>
#include <math.h>

#define N_NODES 50000
#define N_EDGES 800000
#define D_IN    128
#define D1      150
#define D1P     160   // padded
#define D2      100
#define D2P     112   // padded (halves of 224)
#define H2P     128   // h2 padded stride
#define D_OUT   64
#define BK      32

typedef unsigned long long u64;

// ---------------- scratch (device globals) -----------------------------------
__device__ int   g_deg_out_i[N_NODES];
__device__ int   g_deg_in_i [N_NODES];
__device__ int   g_rowoff[N_NODES];
__device__ int   g_fill  [N_NODES];
__device__ int   g_total;
__device__ int   g_csr[N_EDGES];
__device__ float g_norm_out[N_NODES];

__device__ float g_W1p[128 * 160];        // W1 padded 150->160
__device__ float g_b1p[160];
__device__ float g_W2p[160 * 224];        // [Wn pad 112 | Ws pad 112], K pad 150->160
__device__ float g_b2p[112];
__device__ float g_W3p[128 * 64];         // W3 K pad 100->128

__device__ float g_agg[(size_t)N_NODES * D_IN];
__device__ float g_h1 [(size_t)N_NODES * D1P];
__device__ float g_p  [(size_t)N_NODES * D2P];
__device__ float g_s  [(size_t)N_NODES * D2P];
__device__ float g_h2 [(size_t)N_NODES * H2P];

__device__ __forceinline__ float elu(float v) { return v > 0.f ? v : expm1f(v); }

__device__ __forceinline__ void ffma2(u64 &d, u64 a, u64 b) {
    asm("fma.rn.f32x2 %0, %1, %2, %0;" : "+l"(d) : "l"(a), "l"(b));
}
__device__ __forceinline__ u64 dup2(float a) {
    u64 r; asm("mov.b64 %0, {%1, %1};" : "=l"(r) : "f"(a)); return r;
}
__device__ __forceinline__ float2 unp(u64 v) {
    float2 r; asm("mov.b64 {%0, %1}, %2;" : "=f"(r.x), "=f"(r.y) : "l"(v)); return r;
}

// ---------------- prep: pad weights, zero counters ---------------------------
__global__ void prep_kernel(const float* __restrict__ W1, const float* __restrict__ b1,
                            const float* __restrict__ Wn, const float* __restrict__ Ws,
                            const float* __restrict__ b2, const float* __restrict__ W3) {
    int stride = gridDim.x * blockDim.x;
    int t0 = blockIdx.x * blockDim.x + threadIdx.x;
    for (int i = t0; i < 128 * 160; i += stride) {
        int k = i / 160, c = i % 160;
        g_W1p[i] = (c < D1) ? W1[k * D1 + c] : 0.f;
    }
    for (int i = t0; i < 160; i += stride) g_b1p[i] = (i < D1) ? b1[i] : 0.f;
    for (int i = t0; i < 160 * 224; i += stride) {
        int k = i / 224, c = i % 224;
        float v = 0.f;
        if (k < D1) {
            if (c < D2)                      v = Wn[k * D2 + c];
            else if (c >= 112 && c < 112 + D2) v = Ws[k * D2 + (c - 112)];
        }
        g_W2p[i] = v;
    }
    for (int i = t0; i < 112; i += stride) g_b2p[i] = (i < D2) ? b2[i] : 0.f;
    for (int i = t0; i < 128 * 64; i += stride) {
        int k = i / 64, c = i % 64;
        g_W3p[i] = (k < D2) ? W3[k * 64 + c] : 0.f;
    }
    for (int i = t0; i < N_NODES; i += stride) {
        g_deg_out_i[i] = 0;
        g_deg_in_i[i]  = 0;
    }
    if (t0 == 0) g_total = 0;
}

// ---------------- degrees ----------------------------------------------------
__global__ void degree_kernel(const int* __restrict__ src, const int* __restrict__ dst) {
    int i = blockIdx.x * blockDim.x + threadIdx.x;
    if (i < N_EDGES) {
        atomicAdd(&g_deg_out_i[src[i]], 1);
        atomicAdd(&g_deg_in_i [dst[i]], 1);
    }
}

// ---------------- row offsets via warp-aggregated atomic ---------------------
__global__ void rowoff_kernel() {
    int i = blockIdx.x * blockDim.x + threadIdx.x;
    int lane = threadIdx.x & 31;
    int d = (i < N_NODES) ? g_deg_in_i[i] : 0;
    int x = d;
#pragma unroll
    for (int off = 1; off < 32; off <<= 1) {
        int t = __shfl_up_sync(0xffffffffu, x, off);
        if (lane >= off) x += t;
    }
    int excl = x - d;
    int total = __shfl_sync(0xffffffffu, x, 31);
    int base = 0;
    if (lane == 0) base = atomicAdd(&g_total, total);
    base = __shfl_sync(0xffffffffu, base, 0);
    if (i < N_NODES) {
        int o = base + excl;
        g_rowoff[i] = o;
        g_fill[i]   = o;
        g_norm_out[i] = rsqrtf(fmaxf((float)g_deg_out_i[i], 1.f));
    }
}

__global__ void bucket_kernel(const int* __restrict__ src, const int* __restrict__ dst) {
    int i = blockIdx.x * blockDim.x + threadIdx.x;
    if (i < N_EDGES) {
        int pos = atomicAdd(&g_fill[dst[i]], 1);
        g_csr[pos] = src[i];
    }
}

// ---------------- gather 1: agg[d] = norm_in[d] * sum x[s]*norm_out[s] -------
__global__ void gather1_kernel(const float* __restrict__ x) {
    int w    = (blockIdx.x * blockDim.x + threadIdx.x) >> 5;
    int lane = threadIdx.x & 31;
    if (w >= N_NODES) return;
    int beg = g_rowoff[w];
    int cnt = g_deg_in_i[w];
    float4 acc = make_float4(0.f, 0.f, 0.f, 0.f);
    for (int base = 0; base < cnt; base += 32) {
        int idx = base + lane;
        int s = 0; float ns = 0.f;
        if (idx < cnt) { s = g_csr[beg + idx]; ns = g_norm_out[s]; }
        int m = min(32, cnt - base);
        for (int j = 0; j < m; j++) {
            int   sj  = __shfl_sync(0xffffffffu, s,  j);
            float nsj = __shfl_sync(0xffffffffu, ns, j);
            float4 v = __ldg((const float4*)(x + (size_t)sj * D_IN) + lane);
            acc.x = fmaf(v.x, nsj, acc.x);
            acc.y = fmaf(v.y, nsj, acc.y);
            acc.z = fmaf(v.z, nsj, acc.z);
            acc.w = fmaf(v.w, nsj, acc.w);
        }
    }
    float nin = rsqrtf(fmaxf((float)cnt, 1.f));
    acc.x *= nin; acc.y *= nin; acc.z *= nin; acc.w *= nin;
    ((float4*)(g_agg + (size_t)w * D_IN))[lane] = acc;
}

// ---------------- GEMM1: h1 = ELU(agg @ W1p + b1p)  [N,128]->[N,160] ---------
// 80 thr: 8 rg x 10 cg, TM=8, TN=16, FFMA2 accumulators
__global__ __launch_bounds__(80) void gemm1_kernel() {
    __shared__ float As[64][36];
    __shared__ float Bs[BK][160];
    int tid = threadIdx.x;
    int row0 = blockIdx.x * 64;
    int rg = tid / 10, cg = tid % 10;
    u64 acc[8][8];
#pragma unroll
    for (int i = 0; i < 8; i++)
#pragma unroll
        for (int j = 0; j < 8; j++) acc[i][j] = 0ull;

    for (int k0 = 0; k0 < 128; k0 += BK) {
        for (int idx = tid; idx < 512; idx += 80) {
            int r = idx >> 3, c4 = idx & 7;
            float4 v = make_float4(0.f, 0.f, 0.f, 0.f);
            if (row0 + r < N_NODES)
                v = *(const float4*)&g_agg[(size_t)(row0 + r) * D_IN + k0 + c4 * 4];
            *(float4*)&As[r][c4 * 4] = v;
        }
        for (int idx = tid; idx < 1280; idx += 80) {
            int r = idx / 40, c4 = idx % 40;
            *(float4*)&Bs[r][c4 * 4] = *(const float4*)&g_W1p[(k0 + r) * 160 + c4 * 4];
        }
        __syncthreads();
#pragma unroll 2
        for (int kk = 0; kk < BK; kk += 4) {
            float4 a4[8];
#pragma unroll
            for (int i = 0; i < 8; i++) a4[i] = *(const float4*)&As[rg * 8 + i][kk];
#pragma unroll
            for (int q = 0; q < 4; q++) {
                const float* bp = &Bs[kk + q][cg * 16];
                u64 b[8];
#pragma unroll
                for (int t = 0; t < 4; t++) {
                    ulonglong2 v = *(const ulonglong2*)(bp + t * 4);
                    b[t * 2] = v.x; b[t * 2 + 1] = v.y;
                }
#pragma unroll
                for (int i = 0; i < 8; i++) {
                    float a = (q == 0) ? a4[i].x : (q == 1) ? a4[i].y : (q == 2) ? a4[i].z : a4[i].w;
                    u64 a2 = dup2(a);
#pragma unroll
                    for (int j = 0; j < 8; j++) ffma2(acc[i][j], a2, b[j]);
                }
            }
        }
        __syncthreads();
    }
#pragma unroll
    for (int i = 0; i < 8; i++) {
        int g = row0 + rg * 8 + i;
        if (g >= N_NODES) continue;
        float* hp = &g_h1[(size_t)g * D1P + cg * 16];
        const float* bb = &g_b1p[cg * 16];
#pragma unroll
        for (int j = 0; j < 8; j++) {
            float2 v = unp(acc[i][j]);
            hp[j * 2]     = elu(v.x + bb[j * 2]);
            hp[j * 2 + 1] = elu(v.y + bb[j * 2 + 1]);
        }
    }
}

// ---------------- GEMM2 fused: p = h1@Wn, s = h1@Ws  [N,160]->[N,112]x2 ------
// 112 thr: 8 rg x 14 cg, BN=224 (p: cg<7, s: cg>=7)
__global__ __launch_bounds__(112) void gemm2_kernel() {
    __shared__ float As[64][36];
    __shared__ float Bs[BK][224];
    int tid = threadIdx.x;
    int row0 = blockIdx.x * 64;
    int rg = tid / 14, cg = tid % 14;
    u64 acc[8][8];
#pragma unroll
    for (int i = 0; i < 8; i++)
#pragma unroll
        for (int j = 0; j < 8; j++) acc[i][j] = 0ull;

    for (int k0 = 0; k0 < 160; k0 += BK) {
        for (int idx = tid; idx < 512; idx += 112) {
            int r = idx >> 3, c4 = idx & 7;
            float4 v = make_float4(0.f, 0.f, 0.f, 0.f);
            if (row0 + r < N_NODES)
                v = *(const float4*)&g_h1[(size_t)(row0 + r) * D1P + k0 + c4 * 4];
            *(float4*)&As[r][c4 * 4] = v;
        }
        for (int idx = tid; idx < 1792; idx += 112) {
            int r = idx / 56, c4 = idx % 56;
            *(float4*)&Bs[r][c4 * 4] = *(const float4*)&g_W2p[(k0 + r) * 224 + c4 * 4];
        }
        __syncthreads();
#pragma unroll 2
        for (int kk = 0; kk < BK; kk += 4) {
            float4 a4[8];
#pragma unroll
            for (int i = 0; i < 8; i++) a4[i] = *(const float4*)&As[rg * 8 + i][kk];
#pragma unroll
            for (int q = 0; q < 4; q++) {
                const float* bp = &Bs[kk + q][cg * 16];
                u64 b[8];
#pragma unroll
                for (int t = 0; t < 4; t++) {
                    ulonglong2 v = *(const ulonglong2*)(bp + t * 4);
                    b[t * 2] = v.x; b[t * 2 + 1] = v.y;
                }
#pragma unroll
                for (int i = 0; i < 8; i++) {
                    float a = (q == 0) ? a4[i].x : (q == 1) ? a4[i].y : (q == 2) ? a4[i].z : a4[i].w;
                    u64 a2 = dup2(a);
#pragma unroll
                    for (int j = 0; j < 8; j++) ffma2(acc[i][j], a2, b[j]);
                }
            }
        }
        __syncthreads();
    }
#pragma unroll
    for (int i = 0; i < 8; i++) {
        int g = row0 + rg * 8 + i;
        if (g >= N_NODES) continue;
        float* base = (cg < 7) ? &g_p[(size_t)g * D2P + cg * 16]
                               : &g_s[(size_t)g * D2P + (cg - 7) * 16];
#pragma unroll
        for (int j = 0; j < 8; j++) {
            float2 v = unp(acc[i][j]);
            base[j * 2]     = v.x;
            base[j * 2 + 1] = v.y;
        }
    }
}

// ---------------- gather 2 + SAGE epilogue: h2 = ELU(s + mean(p) + b2) -------
__global__ void gather2_kernel() {
    int w    = (blockIdx.x * blockDim.x + threadIdx.x) >> 5;
    int lane = threadIdx.x & 31;
    if (w >= N_NODES) return;
    int beg = g_rowoff[w];
    int cnt = g_deg_in_i[w];
    bool act = lane < (D2P / 4);   // 28 active lanes
    float4 acc = make_float4(0.f, 0.f, 0.f, 0.f);
    for (int base = 0; base < cnt; base += 32) {
        int idx = base + lane;
        int s = (idx < cnt) ? g_csr[beg + idx] : 0;
        int m = min(32, cnt - base);
        for (int j = 0; j < m; j++) {
            int sj = __shfl_sync(0xffffffffu, s, j);
            if (act) {
                float4 v = __ldg((const float4*)(g_p + (size_t)sj * D2P) + lane);
                acc.x += v.x; acc.y += v.y; acc.z += v.z; acc.w += v.w;
            }
        }
    }
    float4 o = make_float4(0.f, 0.f, 0.f, 0.f);
    if (act) {
        float invd = 1.f / fmaxf((float)cnt, 1.f);
        float4 sv = *(const float4*)(g_s + (size_t)w * D2P + lane * 4);
        float4 bv = *(const float4*)(g_b2p + lane * 4);
        o.x = elu(acc.x * invd + sv.x + bv.x);
        o.y = elu(acc.y * invd + sv.y + bv.y);
        o.z = elu(acc.z * invd + sv.z + bv.z);
        o.w = elu(acc.w * invd + sv.w + bv.w);
    }
    *(float4*)(g_h2 + (size_t)w * H2P + lane * 4) = o;
}

// ---------------- GEMM3: out = ELU(h2 @ W3p + b3)  [N,128]->[N,64] -----------
// 128 thr: 32 rg x 4 cg, BM=256, TM=8, TN=16
__global__ __launch_bounds__(128) void gemm3_kernel(const float* __restrict__ b3,
                                                    float* __restrict__ out) {
    __shared__ float As[256][36];
    __shared__ float Bs[BK][64];
    int tid = threadIdx.x;
    int row0 = blockIdx.x * 256;
    int rg = tid / 4, cg = tid % 4;
    u64 acc[8][8];
#pragma unroll
    for (int i = 0; i < 8; i++)
#pragma unroll
        for (int j = 0; j < 8; j++) acc[i][j] = 0ull;

    for (int k0 = 0; k0 < 128; k0 += BK) {
        for (int idx = tid; idx < 2048; idx += 128) {
            int r = idx >> 3, c4 = idx & 7;
            float4 v = make_float4(0.f, 0.f, 0.f, 0.f);
            if (row0 + r < N_NODES)
                v = *(const float4*)&g_h2[(size_t)(row0 + r) * H2P + k0 + c4 * 4];
            *(float4*)&As[r][c4 * 4] = v;
        }
        for (int idx = tid; idx < 512; idx += 128) {
            int r = idx >> 4, c4 = idx & 15;
            *(float4*)&Bs[r][c4 * 4] = *(const float4*)&g_W3p[(k0 + r) * 64 + c4 * 4];
        }
        __syncthreads();
#pragma unroll 2
        for (int kk = 0; kk < BK; kk += 4) {
            float4 a4[8];
#pragma unroll
            for (int i = 0; i < 8; i++) a4[i] = *(const float4*)&As[rg * 8 + i][kk];
#pragma unroll
            for (int q = 0; q < 4; q++) {
                const float* bp = &Bs[kk + q][cg * 16];
                u64 b[8];
#pragma unroll
                for (int t = 0; t < 4; t++) {
                    ulonglong2 v = *(const ulonglong2*)(bp + t * 4);
                    b[t * 2] = v.x; b[t * 2 + 1] = v.y;
                }
#pragma unroll
                for (int i = 0; i < 8; i++) {
                    float a = (q == 0) ? a4[i].x : (q == 1) ? a4[i].y : (q == 2) ? a4[i].z : a4[i].w;
                    u64 a2 = dup2(a);
#pragma unroll
                    for (int j = 0; j < 8; j++) ffma2(acc[i][j], a2, b[j]);
                }
            }
        }
        __syncthreads();
    }
#pragma unroll
    for (int i = 0; i < 8; i++) {
        int g = row0 + rg * 8 + i;
        if (g >= N_NODES) continue;
        float* op = &out[(size_t)g * D_OUT + cg * 16];
        const float* bb = &b3[cg * 16];
#pragma unroll
        for (int j = 0; j < 8; j++) {
            float2 v = unp(acc[i][j]);
            op[j * 2]     = elu(v.x + bb[j * 2]);
            op[j * 2 + 1] = elu(v.y + bb[j * 2 + 1]);
        }
    }
}

// ---------------- launch -----------------------------------------------------
extern "C" void kernel_launch(void* const* d_in, const int* in_sizes, int n_in,
                              void* d_out, int out_size) {
    const float* x   = (const float*)d_in[0];
    const int*   src = (const int*)d_in[1];
    const int*   dst = (const int*)d_in[2];
    const float* W1  = (const float*)d_in[3];
    const float* b1  = (const float*)d_in[4];
    const float* Wn  = (const float*)d_in[5];
    const float* Ws  = (const float*)d_in[6];
    const float* b2  = (const float*)d_in[7];
    const float* W3  = (const float*)d_in[8];
    const float* b3  = (const float*)d_in[9];
    float* out = (float*)d_out;

    const int ROW_BLOCKS  = (N_NODES + 63) / 64;        // 782
    const int EDGE_BLOCKS = (N_EDGES + 255) / 256;      // 3125
    const int WARP_BLOCKS = (N_NODES * 32 + 255) / 256; // 6250

    prep_kernel<<<256, 256>>>(W1, b1, Wn, Ws, b2, W3);
    degree_kernel<<<EDGE_BLOCKS, 256>>>(src, dst);
    rowoff_kernel<<<(N_NODES + 255) / 256, 256>>>();
    bucket_kernel<<<EDGE_BLOCKS, 256>>>(src, dst);
    gather1_kernel<<<WARP_BLOCKS, 256>>>(x);
    gemm1_kernel<<<ROW_BLOCKS, 80>>>();
    gemm2_kernel<<<ROW_BLOCKS, 112>>>();
    gather2_kernel<<<WARP_BLOCKS, 256>>>();
    gemm3_kernel<<<(N_NODES + 255) / 256, 128>>>(b3, out);
}